// round 1
// baseline (speedup 1.0000x reference)
#include <cuda_runtime.h>
#include <cstdint>

// Problem dims (fixed)
#define E_  100
#define B_  1024
#define D_  2048
#define H1_ 512
#define H2_ 256

// Scratch for intermediates (no cudaMalloc allowed)
__device__ float g_h1[(size_t)E_ * B_ * H1_];  // [E,B,H1] 210MB
__device__ float g_h2[(size_t)E_ * B_ * H2_];  // [E,B,H2] 105MB

// ---------------- smem layout constants ----------------
#define A_ST 36            // padded row stride (floats) for A tile [128][36]
#define B_ST 132           // padded row stride (floats) for B tile [32][132]
#define A_TILE_F (128 * A_ST)   // 4608 floats
#define B_TILE_F (32 * B_ST)    // 4224 floats
#define SMEM_FLOATS (2 * A_TILE_F + 2 * B_TILE_F)  // 17664 floats = 70656 B

__device__ __forceinline__ void cp_async16(float* smem_dst, const float* gmem_src) {
    uint32_t s = (uint32_t)__cvta_generic_to_shared(smem_dst);
    asm volatile("cp.async.cg.shared.global [%0], [%1], 16;\n" :: "r"(s), "l"(gmem_src));
}
__device__ __forceinline__ void cp_commit() {
    asm volatile("cp.async.commit_group;\n" ::: "memory");
}
__device__ __forceinline__ void cp_wait_all() {
    asm volatile("cp.async.wait_group 0;\n" ::: "memory");
}

__device__ __forceinline__ uint32_t f2tf32(float f) {
    uint32_t r;
    asm("cvt.rna.tf32.f32 %0, %1;" : "=r"(r) : "f"(f));
    return r;
}

__device__ __forceinline__ void mma_tf32(float c[4], const uint32_t a[4], const uint32_t b[2]) {
    asm volatile(
        "mma.sync.aligned.m16n8k8.row.col.f32.tf32.tf32.f32 "
        "{%0,%1,%2,%3}, {%4,%5,%6,%7}, {%8,%9}, {%0,%1,%2,%3};"
        : "+f"(c[0]), "+f"(c[1]), "+f"(c[2]), "+f"(c[3])
        : "r"(a[0]), "r"(a[1]), "r"(a[2]), "r"(a[3]),
          "r"(b[0]), "r"(b[1]));
}

// Batched GEMM: C[e] = act(A[e] @ B[e] + bias[e])
//   A[e]: [M,K] row-major, lda = K, expert stride strideA (0 => shared A)
//   B[e]: [K,N] row-major, ldb = N, expert stride strideB
//   bias[e]: [N], expert stride N
//   C[e]: [M,N] row-major, ldc = N, expert stride strideC
// Grid: (N/128, M/128, E). Block: 256 threads (8 warps, 2x4 warp tiling,
// warp tile 64x32, mma m16n8k8 tf32).
template <bool RELU>
__global__ void __launch_bounds__(256, 2)
gemm_tf32_kernel(const float* __restrict__ A, const float* __restrict__ Bw,
                 const float* __restrict__ bias, float* __restrict__ C,
                 int M, int N, int K,
                 long strideA, long strideB, long strideC) {
    extern __shared__ float smem[];

    const int tid  = threadIdx.x;
    const int lane = tid & 31;
    const int warp = tid >> 5;
    const int wm   = warp >> 2;   // 0..1
    const int wn   = warp & 3;    // 0..3

    const int e  = blockIdx.z;
    const int bm = blockIdx.y;
    const int bn = blockIdx.x;

    const float* Ag = A  + (size_t)e * strideA + (size_t)bm * 128 * K;   // lda = K
    const float* Bg = Bw + (size_t)e * strideB + (size_t)bn * 128;       // ldb = N
    const int lda = K;
    const int ldb = N;

    float acc[4][4][4];
    #pragma unroll
    for (int i = 0; i < 4; i++)
        #pragma unroll
        for (int j = 0; j < 4; j++)
            #pragma unroll
            for (int r = 0; r < 4; r++) acc[i][j][r] = 0.0f;

    const int KC = K >> 5;  // K / 32

    // ---- tile loader (one 32-deep k chunk) ----
    auto load_tiles = [&](int buf, int kc) {
        float* sA = smem + buf * A_TILE_F;
        float* sB = smem + 2 * A_TILE_F + buf * B_TILE_F;
        const float* Abase = Ag + kc * 32;
        #pragma unroll
        for (int i = 0; i < 4; i++) {
            int q  = tid + i * 256;            // 0..1023 float4 slots
            int r  = q >> 3;                   // 0..127
            int c4 = (q & 7) * 4;              // 0..28
            cp_async16(sA + r * A_ST + c4, Abase + (size_t)r * lda + c4);
        }
        const float* Bbase = Bg + (size_t)(kc * 32) * ldb;
        #pragma unroll
        for (int i = 0; i < 4; i++) {
            int q  = tid + i * 256;
            int r  = q >> 5;                   // 0..31
            int c4 = (q & 31) * 4;             // 0..124
            cp_async16(sB + r * B_ST + c4, Bbase + (size_t)r * ldb + c4);
        }
    };

    load_tiles(0, 0);
    cp_commit();

    for (int kc = 0; kc < KC; kc++) {
        const int cur = kc & 1;
        cp_wait_all();
        __syncthreads();
        if (kc + 1 < KC) {
            load_tiles(cur ^ 1, kc + 1);
            cp_commit();
        }

        const float* sA = smem + cur * A_TILE_F;
        const float* sB = smem + 2 * A_TILE_F + cur * B_TILE_F;

        #pragma unroll
        for (int kk = 0; kk < 4; kk++) {
            const int k0 = kk * 8;
            uint32_t afr[4][4];
            uint32_t bfr[4][2];
            #pragma unroll
            for (int i = 0; i < 4; i++) {
                const float* p = sA + (wm * 64 + i * 16 + (lane >> 2)) * A_ST + k0 + (lane & 3);
                afr[i][0] = f2tf32(p[0]);
                afr[i][1] = f2tf32(p[8 * A_ST]);
                afr[i][2] = f2tf32(p[4]);
                afr[i][3] = f2tf32(p[8 * A_ST + 4]);
            }
            #pragma unroll
            for (int j = 0; j < 4; j++) {
                const float* p = sB + (k0 + (lane & 3)) * B_ST + wn * 32 + j * 8 + (lane >> 2);
                bfr[j][0] = f2tf32(p[0]);
                bfr[j][1] = f2tf32(p[4 * B_ST]);
            }
            #pragma unroll
            for (int i = 0; i < 4; i++)
                #pragma unroll
                for (int j = 0; j < 4; j++)
                    mma_tf32(acc[i][j], afr[i], bfr[j]);
        }
        __syncthreads();
    }

    // ---- epilogue: bias + relu + store ----
    const float* be = bias + (size_t)e * N + bn * 128;
    float* Ce = C + (size_t)e * strideC + (size_t)(bm * 128) * N + bn * 128;

    #pragma unroll
    for (int j = 0; j < 4; j++) {
        const int c0 = wn * 32 + j * 8 + (lane & 3) * 2;
        const float bv0 = be[c0];
        const float bv1 = be[c0 + 1];
        #pragma unroll
        for (int i = 0; i < 4; i++) {
            const int r0 = wm * 64 + i * 16 + (lane >> 2);
            float2 v0, v1;
            v0.x = acc[i][j][0] + bv0;
            v0.y = acc[i][j][1] + bv1;
            v1.x = acc[i][j][2] + bv0;
            v1.y = acc[i][j][3] + bv1;
            if (RELU) {
                v0.x = fmaxf(v0.x, 0.0f); v0.y = fmaxf(v0.y, 0.0f);
                v1.x = fmaxf(v1.x, 0.0f); v1.y = fmaxf(v1.y, 0.0f);
            }
            *reinterpret_cast<float2*>(Ce + (size_t)r0 * N + c0)       = v0;
            *reinterpret_cast<float2*>(Ce + (size_t)(r0 + 8) * N + c0) = v1;
        }
    }
}

// Layer 3: out[b*E + e] = dot(h2[e][b][:], W3[e][:,0]) + b3[e]
// One warp per (e,b).
__global__ void __launch_bounds__(256)
layer3_kernel(const float* __restrict__ h2, const float* __restrict__ W3,
              const float* __restrict__ b3, float* __restrict__ out) {
    const int gw   = (blockIdx.x * blockDim.x + threadIdx.x) >> 5;
    const int lane = threadIdx.x & 31;
    if (gw >= E_ * B_) return;
    const int e = gw / B_;
    const int b = gw % B_;

    const float* h = h2 + ((size_t)e * B_ + b) * H2_;
    const float* w = W3 + (size_t)e * H2_;

    float s = 0.0f;
    #pragma unroll
    for (int i = 0; i < H2_ / 32; i++)
        s += h[lane + 32 * i] * w[lane + 32 * i];

    #pragma unroll
    for (int o = 16; o > 0; o >>= 1)
        s += __shfl_xor_sync(0xFFFFFFFFu, s, o);

    if (lane == 0)
        out[(size_t)b * E_ + e] = s + b3[e];
}

extern "C" void kernel_launch(void* const* d_in, const int* in_sizes, int n_in,
                              void* d_out, int out_size) {
    const float* x  = (const float*)d_in[0];
    const float* W1 = (const float*)d_in[1];
    const float* b1 = (const float*)d_in[2];
    const float* W2 = (const float*)d_in[3];
    const float* b2 = (const float*)d_in[4];
    const float* W3 = (const float*)d_in[5];
    const float* b3 = (const float*)d_in[6];
    float* out = (float*)d_out;

    float* h1 = nullptr;
    float* h2 = nullptr;
    cudaGetSymbolAddress((void**)&h1, g_h1);
    cudaGetSymbolAddress((void**)&h2, g_h2);

    const int smem_bytes = SMEM_FLOATS * sizeof(float);  // 70656
    cudaFuncSetAttribute(gemm_tf32_kernel<true>,
                         cudaFuncAttributeMaxDynamicSharedMemorySize, smem_bytes);

    dim3 blk(256);

    // Layer 1: [1024,2048] x [2048,512] per expert, relu
    {
        dim3 grid(H1_ / 128, B_ / 128, E_);  // (4, 8, 100)
        gemm_tf32_kernel<true><<<grid, blk, smem_bytes>>>(
            x, W1, b1, h1,
            B_, H1_, D_,
            0L, (long)D_ * H1_, (long)B_ * H1_);
    }

    // Layer 2: [1024,512] x [512,256] per expert, relu
    {
        dim3 grid(H2_ / 128, B_ / 128, E_);  // (2, 8, 100)
        gemm_tf32_kernel<true><<<grid, blk, smem_bytes>>>(
            h1, W2, b2, h2,
            B_, H2_, H1_,
            (long)B_ * H1_, (long)H1_ * H2_, (long)B_ * H2_);
    }

    // Layer 3: dot products + bias
    {
        const int warps = E_ * B_;            // 102400
        const int blocks = warps / 8;         // 12800 (256 threads = 8 warps)
        layer3_kernel<<<blocks, blk>>>(h2, W3, b3, out);
    }
}

// round 4
// speedup vs baseline: 2.0467x; 2.0467x over previous
#include <cuda_runtime.h>
#include <cuda_fp16.h>
#include <cstdint>

// ---------------- problem dims ----------------
#define E_  100
#define B_  1024
#define D_  2048
#define H1_ 512
#define H2_ 256

// ---------------- scratch (__device__ globals; no cudaMalloc allowed) ----
__device__ __half g_xh [(size_t)B_ * D_];          //   4MB
__device__ __half g_w1h[(size_t)E_ * D_ * H1_];    // 210MB
__device__ __half g_w2h[(size_t)E_ * H1_ * H2_];   //  26MB
__device__ __half g_h1h[(size_t)E_ * B_ * H1_];    // 105MB
__device__ __half g_h2h[(size_t)E_ * B_ * H2_];    //  52MB

// ---------------- device helpers ----------------
__device__ __forceinline__ uint32_t smem_u32(const void* p) {
    uint32_t a;
    asm("{ .reg .u64 t; cvta.to.shared.u64 t, %1; cvt.u32.u64 %0, t; }" : "=r"(a) : "l"(p));
    return a;
}
__device__ __forceinline__ void cp_async16(uint32_t s, const void* g) {
    asm volatile("cp.async.cg.shared.global [%0], [%1], 16;" :: "r"(s), "l"(g));
}
__device__ __forceinline__ void cp_commit() {
    asm volatile("cp.async.commit_group;" ::: "memory");
}
__device__ __forceinline__ void ldsm4(uint32_t r[4], uint32_t addr) {
    asm volatile("ldmatrix.sync.aligned.m8n8.x4.shared.b16 {%0,%1,%2,%3}, [%4];"
        : "=r"(r[0]), "=r"(r[1]), "=r"(r[2]), "=r"(r[3]) : "r"(addr));
}
__device__ __forceinline__ void ldsm4t(uint32_t& r0, uint32_t& r1, uint32_t& r2, uint32_t& r3,
                                       uint32_t addr) {
    asm volatile("ldmatrix.sync.aligned.m8n8.x4.trans.shared.b16 {%0,%1,%2,%3}, [%4];"
        : "=r"(r0), "=r"(r1), "=r"(r2), "=r"(r3) : "r"(addr));
}
__device__ __forceinline__ void mma_f16(float c[4], const uint32_t a[4], const uint32_t b[2]) {
    asm volatile(
        "mma.sync.aligned.m16n8k16.row.col.f32.f16.f16.f32 "
        "{%0,%1,%2,%3}, {%4,%5,%6,%7}, {%8,%9}, {%0,%1,%2,%3};"
        : "+f"(c[0]), "+f"(c[1]), "+f"(c[2]), "+f"(c[3])
        : "r"(a[0]), "r"(a[1]), "r"(a[2]), "r"(a[3]), "r"(b[0]), "r"(b[1]));
}

// ---------------- GEMM: C[e] = relu(A[e] @ B[e] + bias[e]) in fp16 -------
// CTA tile 256(M) x 128(N), K chunk 64. 512 threads = 16 warps (4m x 4n),
// warp tile 64x32 -> 16 mma(m16n8k16) per k-step, 4 k-steps per chunk.
// A gmem [M,K] fp16 row-major; B gmem [K,N] fp16 row-major (ldmatrix.trans).
#define MT 256
#define NT 128
#define KC 64
#define A_STRIDE 144                 // 64 fp16 = 128B data + 16B pad
#define B_STRIDE 272                 // 128 fp16 = 256B data + 16B pad
#define A_TILE_B (MT * A_STRIDE)     // 36864
#define B_TILE_B (KC * B_STRIDE)     // 17408
#define STAGE_B  (A_TILE_B + B_TILE_B)
#define NSTAGE 3
#define SM_TILE_OFF 512
#define SMEM_TOT (SM_TILE_OFF + NSTAGE * STAGE_B)   // 163328

__global__ void __launch_bounds__(512, 1)
gemm_f16(const __half* __restrict__ A, const __half* __restrict__ Bw,
         const float* __restrict__ bias, __half* __restrict__ C,
         int nch, int ArowsPerE, int Ntot, unsigned long long strideCe) {
    extern __shared__ __align__(128) char smem[];
    float* bias_s = reinterpret_cast<float*>(smem);
    const uint32_t sbase = smem_u32(smem) + SM_TILE_OFF;
    const int tid = threadIdx.x, lane = tid & 31, warp = tid >> 5;
    const int wm = warp >> 2, wn = warp & 3;
    const int e = blockIdx.z, mt = blockIdx.y, nt = blockIdx.x;
    const int n0 = nt * NT;
    const int K = nch * KC;

    if (tid < NT) bias_s[tid] = bias[(size_t)e * Ntot + n0 + tid];

    const char* Ab = (const char*)(A + ((size_t)e * ArowsPerE + (size_t)mt * MT) * K);
    const char* Bb = (const char*)(Bw + (size_t)e * (size_t)K * Ntot + n0);
    const int ldaB = K * 2;
    const int ldbB = Ntot * 2;

    auto load_stage = [&](int s, int c) {
        const uint32_t st = sbase + s * STAGE_B;
        const char* Ac = Ab + c * KC * 2;
        #pragma unroll
        for (int it = 0; it < 4; it++) {
            int q = tid + it * 512;              // 0..2047
            int r = q >> 3, seg = (q & 7) * 16;
            cp_async16(st + r * A_STRIDE + seg, Ac + (size_t)r * ldaB + seg);
        }
        const char* Bc = Bb + (size_t)(c * KC) * ldbB;
        const uint32_t stb = st + A_TILE_B;
        #pragma unroll
        for (int it = 0; it < 2; it++) {
            int q = tid + it * 512;              // 0..1023
            int r = q >> 4, seg = (q & 15) * 16;
            cp_async16(stb + r * B_STRIDE + seg, Bc + (size_t)r * ldbB + seg);
        }
    };

    load_stage(0, 0); cp_commit();
    load_stage(1, 1); cp_commit();

    float acc[4][4][4];
    #pragma unroll
    for (int i = 0; i < 4; i++)
        #pragma unroll
        for (int j = 0; j < 4; j++)
            #pragma unroll
            for (int r = 0; r < 4; r++) acc[i][j][r] = 0.0f;

    // per-lane ldmatrix offsets (bytes)
    const uint32_t offA = (uint32_t)(lane & 15) * A_STRIDE + (uint32_t)(lane >> 4) * 16;
    const uint32_t offB = (uint32_t)(lane & 15) * B_STRIDE + (uint32_t)(lane >> 4) * 16;
    const uint32_t awoff = (uint32_t)wm * 64 * A_STRIDE + offA;
    const uint32_t bwoff = (uint32_t)wn * 64 + offB;          // wn*32 cols * 2B

    for (int c = 0; c < nch; c++) {
        if (c + 1 < nch) { asm volatile("cp.async.wait_group 1;" ::: "memory"); }
        else             { asm volatile("cp.async.wait_group 0;" ::: "memory"); }
        __syncthreads();
        if (c + 2 < nch) { load_stage((c + 2) % NSTAGE, c + 2); cp_commit(); }

        const uint32_t st = sbase + (c % NSTAGE) * STAGE_B;
        const uint32_t sa = st + awoff;
        const uint32_t sb = st + A_TILE_B + bwoff;

        #pragma unroll
        for (int ks = 0; ks < 4; ks++) {
            uint32_t a[4][4], b[4][2];
            #pragma unroll
            for (int i = 0; i < 4; i++)
                ldsm4(a[i], sa + (uint32_t)i * (16 * A_STRIDE) + (uint32_t)ks * 32);
            #pragma unroll
            for (int j2 = 0; j2 < 2; j2++) {
                uint32_t r0, r1, r2, r3;
                ldsm4t(r0, r1, r2, r3,
                       sb + (uint32_t)ks * (16 * B_STRIDE) + (uint32_t)j2 * 32);
                b[j2 * 2][0] = r0;     b[j2 * 2][1] = r1;
                b[j2 * 2 + 1][0] = r2; b[j2 * 2 + 1][1] = r3;
            }
            #pragma unroll
            for (int i = 0; i < 4; i++)
                #pragma unroll
                for (int j = 0; j < 4; j++)
                    mma_f16(acc[i][j], a[i], b[j]);
        }
    }

    // ---- epilogue: bias + relu, store fp16 ----
    const int mrow0 = mt * MT + wm * 64 + (lane >> 2);
    const int col0 = wn * 32 + (lane & 3) * 2;
    __half* Ce = C + (size_t)e * strideCe + n0;
    #pragma unroll
    for (int i = 0; i < 4; i++) {
        const size_t r0 = (size_t)(mrow0 + i * 16);
        #pragma unroll
        for (int j = 0; j < 4; j++) {
            const int col = col0 + j * 8;
            const float bx = bias_s[col], by = bias_s[col + 1];
            float v0 = fmaxf(acc[i][j][0] + bx, 0.0f);
            float v1 = fmaxf(acc[i][j][1] + by, 0.0f);
            float v2 = fmaxf(acc[i][j][2] + bx, 0.0f);
            float v3 = fmaxf(acc[i][j][3] + by, 0.0f);
            *reinterpret_cast<__half2*>(Ce + r0 * Ntot + col)       = __floats2half2_rn(v0, v1);
            *reinterpret_cast<__half2*>(Ce + (r0 + 8) * Ntot + col) = __floats2half2_rn(v2, v3);
        }
    }
}

// ---------------- pre-pass: f32 -> f16 (vectorized) ----------------
__global__ void f32_to_f16_kernel(const float4* __restrict__ in, uint2* __restrict__ out,
                                  long n4) {
    long i = blockIdx.x * (long)blockDim.x + threadIdx.x;
    if (i < n4) {
        float4 v = in[i];
        __half2 lo = __floats2half2_rn(v.x, v.y);
        __half2 hi = __floats2half2_rn(v.z, v.w);
        uint2 o;
        o.x = *reinterpret_cast<uint32_t*>(&lo);
        o.y = *reinterpret_cast<uint32_t*>(&hi);
        out[i] = o;
    }
}

// ---------------- layer 3: out[b*E+e] = dot(h2[e,b,:], W3[e,:,0]) + b3[e] ----
__global__ void __launch_bounds__(256)
layer3_kernel(const __half* __restrict__ h2, const float* __restrict__ W3,
              const float* __restrict__ b3, float* __restrict__ out) {
    const int gw = (blockIdx.x * blockDim.x + threadIdx.x) >> 5;
    const int lane = threadIdx.x & 31;
    if (gw >= E_ * B_) return;
    const int e = gw / B_;
    const int b = gw % B_;
    const __half* h = h2 + ((size_t)e * B_ + b) * H2_;
    const float* w = W3 + (size_t)e * H2_;
    float s = 0.0f;
    #pragma unroll
    for (int i = 0; i < H2_ / 32; i++)
        s += __half2float(h[lane + 32 * i]) * w[lane + 32 * i];
    #pragma unroll
    for (int o = 16; o > 0; o >>= 1)
        s += __shfl_xor_sync(0xFFFFFFFFu, s, o);
    if (lane == 0) out[(size_t)b * E_ + e] = s + b3[e];
}

// ---------------- host ----------------
extern "C" void kernel_launch(void* const* d_in, const int* in_sizes, int n_in,
                              void* d_out, int out_size) {
    const float* x  = (const float*)d_in[0];
    const float* W1 = (const float*)d_in[1];
    const float* b1 = (const float*)d_in[2];
    const float* W2 = (const float*)d_in[3];
    const float* b2 = (const float*)d_in[4];
    const float* W3 = (const float*)d_in[5];
    const float* b3 = (const float*)d_in[6];
    float* out = (float*)d_out;

    __half *xh, *w1h, *w2h, *h1h, *h2h;
    cudaGetSymbolAddress((void**)&xh,  g_xh);
    cudaGetSymbolAddress((void**)&w1h, g_w1h);
    cudaGetSymbolAddress((void**)&w2h, g_w2h);
    cudaGetSymbolAddress((void**)&h1h, g_h1h);
    cudaGetSymbolAddress((void**)&h2h, g_h2h);

    cudaFuncSetAttribute(gemm_f16, cudaFuncAttributeMaxDynamicSharedMemorySize, SMEM_TOT);

    // pre-convert to fp16
    {
        long n4x  = (long)B_ * D_ / 4;
        long n4w1 = (long)E_ * D_ * H1_ / 4;
        long n4w2 = (long)E_ * H1_ * H2_ / 4;
        f32_to_f16_kernel<<<(unsigned)((n4x  + 255) / 256), 256>>>((const float4*)x,  (uint2*)xh,  n4x);
        f32_to_f16_kernel<<<(unsigned)((n4w1 + 255) / 256), 256>>>((const float4*)W1, (uint2*)w1h, n4w1);
        f32_to_f16_kernel<<<(unsigned)((n4w2 + 255) / 256), 256>>>((const float4*)W2, (uint2*)w2h, n4w2);
    }

    // layer 1: per-expert [1024,2048] x [2048,512], relu
    {
        dim3 grid(H1_ / NT, B_ / MT, E_);   // (4, 4, 100)
        gemm_f16<<<grid, 512, SMEM_TOT>>>(
            xh, w1h, b1, h1h,
            D_ / KC, /*ArowsPerE=*/0, /*Ntot=*/H1_,
            (unsigned long long)B_ * H1_);
    }
    // layer 2: per-expert [1024,512] x [512,256], relu
    {
        dim3 grid(H2_ / NT, B_ / MT, E_);   // (2, 4, 100)
        gemm_f16<<<grid, 512, SMEM_TOT>>>(
            h1h, w2h, b2, h2h,
            H1_ / KC, /*ArowsPerE=*/B_, /*Ntot=*/H2_,
            (unsigned long long)B_ * H2_);
    }
    // layer 3
    layer3_kernel<<<(E_ * B_) / 8, 256>>>(h2h, W3, b3, out);
}

// round 5
// speedup vs baseline: 2.1468x; 1.0489x over previous
#include <cuda_runtime.h>
#include <cuda_fp16.h>
#include <cstdint>

// ---------------- problem dims ----------------
#define E_  100
#define B_  1024
#define D_  2048
#define H1_ 512
#define H2_ 256

// ---------------- scratch (__device__ globals; no cudaMalloc allowed) ----
__device__ __half g_xh [(size_t)B_ * D_];          //   4MB
__device__ __half g_w1h[(size_t)E_ * D_ * H1_];    // 210MB
__device__ __half g_w2h[(size_t)E_ * H1_ * H2_];   //  26MB
__device__ __half g_h1h[(size_t)E_ * B_ * H1_];    // 105MB
__device__ __half g_h2h[(size_t)E_ * B_ * H2_];    //  52MB

// ---------------- device helpers ----------------
__device__ __forceinline__ uint32_t smem_u32(const void* p) {
    uint32_t a;
    asm("{ .reg .u64 t; cvta.to.shared.u64 t, %1; cvt.u32.u64 %0, t; }" : "=r"(a) : "l"(p));
    return a;
}
__device__ __forceinline__ void cp_async16(uint32_t s, const void* g) {
    asm volatile("cp.async.cg.shared.global [%0], [%1], 16;" :: "r"(s), "l"(g));
}
__device__ __forceinline__ void cp_commit() {
    asm volatile("cp.async.commit_group;" ::: "memory");
}
__device__ __forceinline__ void ldsm4(uint32_t r[4], uint32_t addr) {
    asm volatile("ldmatrix.sync.aligned.m8n8.x4.shared.b16 {%0,%1,%2,%3}, [%4];"
        : "=r"(r[0]), "=r"(r[1]), "=r"(r[2]), "=r"(r[3]) : "r"(addr));
}
__device__ __forceinline__ void ldsm4t(uint32_t& r0, uint32_t& r1, uint32_t& r2, uint32_t& r3,
                                       uint32_t addr) {
    asm volatile("ldmatrix.sync.aligned.m8n8.x4.trans.shared.b16 {%0,%1,%2,%3}, [%4];"
        : "=r"(r0), "=r"(r1), "=r"(r2), "=r"(r3) : "r"(addr));
}
__device__ __forceinline__ void mma_f16(float c[4], const uint32_t a[4], const uint32_t b[2]) {
    asm volatile(
        "mma.sync.aligned.m16n8k16.row.col.f32.f16.f16.f32 "
        "{%0,%1,%2,%3}, {%4,%5,%6,%7}, {%8,%9}, {%0,%1,%2,%3};"
        : "+f"(c[0]), "+f"(c[1]), "+f"(c[2]), "+f"(c[3])
        : "r"(a[0]), "r"(a[1]), "r"(a[2]), "r"(a[3]), "r"(b[0]), "r"(b[1]));
}

// ---------------- GEMM: C[e] = relu(A[e] @ B[e] + bias[e]) in fp16 -------
// CTA tile 128(M) x 128(N), K chunk 64. 256 threads = 8 warps (2m x 4n),
// warp tile 64x32 -> 16 mma(m16n8k16) per k-step, 4 k-steps per chunk.
// 2 CTAs/SM: sync bubbles of one CTA overlap with the other's mma work.
// A gmem [M,K] fp16 row-major; B gmem [K,N] fp16 row-major (ldmatrix.trans).
#define MT 128
#define NT 128
#define KC 64
#define A_STRIDE 144                 // 64 fp16 = 128B data + 16B pad
#define B_STRIDE 272                 // 128 fp16 = 256B data + 16B pad
#define A_TILE_B (MT * A_STRIDE)     // 18432
#define B_TILE_B (KC * B_STRIDE)     // 17408
#define STAGE_B  (A_TILE_B + B_TILE_B)   // 35840
#define NSTAGE 3
#define SM_TILE_OFF 512
#define SMEM_TOT (SM_TILE_OFF + NSTAGE * STAGE_B)   // 108032

__global__ void __launch_bounds__(256, 2)
gemm_f16(const __half* __restrict__ A, const __half* __restrict__ Bw,
         const float* __restrict__ bias, __half* __restrict__ C,
         int nch, int ArowsPerE, int Ntot, unsigned long long strideCe) {
    extern __shared__ __align__(128) char smem[];
    float* bias_s = reinterpret_cast<float*>(smem);
    const uint32_t sbase = smem_u32(smem) + SM_TILE_OFF;
    const int tid = threadIdx.x, lane = tid & 31, warp = tid >> 5;
    const int wm = warp >> 2, wn = warp & 3;
    const int e = blockIdx.z, mt = blockIdx.y, nt = blockIdx.x;
    const int n0 = nt * NT;
    const int K = nch * KC;

    if (tid < NT) bias_s[tid] = bias[(size_t)e * Ntot + n0 + tid];

    const char* Ab = (const char*)(A + ((size_t)e * ArowsPerE + (size_t)mt * MT) * K);
    const char* Bb = (const char*)(Bw + (size_t)e * (size_t)K * Ntot + n0);
    const int ldaB = K * 2;
    const int ldbB = Ntot * 2;

    auto load_stage = [&](int s, int c) {
        const uint32_t st = sbase + s * STAGE_B;
        const char* Ac = Ab + c * KC * 2;
        #pragma unroll
        for (int it = 0; it < 4; it++) {
            int q = tid + it * 256;              // 0..1023 (128 rows x 8 segs)
            int r = q >> 3, seg = (q & 7) * 16;
            cp_async16(st + r * A_STRIDE + seg, Ac + (size_t)r * ldaB + seg);
        }
        const char* Bc = Bb + (size_t)(c * KC) * ldbB;
        const uint32_t stb = st + A_TILE_B;
        #pragma unroll
        for (int it = 0; it < 4; it++) {
            int q = tid + it * 256;              // 0..1023 (64 rows x 16 segs)
            int r = q >> 4, seg = (q & 15) * 16;
            cp_async16(stb + r * B_STRIDE + seg, Bc + (size_t)r * ldbB + seg);
        }
    };

    load_stage(0, 0); cp_commit();
    load_stage(1, 1); cp_commit();

    float acc[4][4][4];
    #pragma unroll
    for (int i = 0; i < 4; i++)
        #pragma unroll
        for (int j = 0; j < 4; j++)
            #pragma unroll
            for (int r = 0; r < 4; r++) acc[i][j][r] = 0.0f;

    // per-lane ldmatrix offsets (bytes)
    const uint32_t offA = (uint32_t)(lane & 15) * A_STRIDE + (uint32_t)(lane >> 4) * 16;
    const uint32_t offB = (uint32_t)(lane & 15) * B_STRIDE + (uint32_t)(lane >> 4) * 16;
    const uint32_t awoff = (uint32_t)wm * 64 * A_STRIDE + offA;
    const uint32_t bwoff = (uint32_t)wn * 64 + offB;          // wn*32 cols * 2B

    for (int c = 0; c < nch; c++) {
        if (c + 1 < nch) { asm volatile("cp.async.wait_group 1;" ::: "memory"); }
        else             { asm volatile("cp.async.wait_group 0;" ::: "memory"); }
        __syncthreads();
        if (c + 2 < nch) { load_stage((c + 2) % NSTAGE, c + 2); cp_commit(); }

        const uint32_t st = sbase + (c % NSTAGE) * STAGE_B;
        const uint32_t sa = st + awoff;
        const uint32_t sb = st + A_TILE_B + bwoff;

        #pragma unroll
        for (int ks = 0; ks < 4; ks++) {
            uint32_t a[4][4], b[4][2];
            #pragma unroll
            for (int i = 0; i < 4; i++)
                ldsm4(a[i], sa + (uint32_t)i * (16 * A_STRIDE) + (uint32_t)ks * 32);
            #pragma unroll
            for (int j2 = 0; j2 < 2; j2++) {
                uint32_t r0, r1, r2, r3;
                ldsm4t(r0, r1, r2, r3,
                       sb + (uint32_t)ks * (16 * B_STRIDE) + (uint32_t)j2 * 32);
                b[j2 * 2][0] = r0;     b[j2 * 2][1] = r1;
                b[j2 * 2 + 1][0] = r2; b[j2 * 2 + 1][1] = r3;
            }
            #pragma unroll
            for (int i = 0; i < 4; i++)
                #pragma unroll
                for (int j = 0; j < 4; j++)
                    mma_f16(acc[i][j], a[i], b[j]);
        }
    }

    // ---- epilogue: bias + relu, store fp16 ----
    const int mrow0 = mt * MT + wm * 64 + (lane >> 2);
    const int col0 = wn * 32 + (lane & 3) * 2;
    __half* Ce = C + (size_t)e * strideCe + n0;
    #pragma unroll
    for (int i = 0; i < 4; i++) {
        const size_t r0 = (size_t)(mrow0 + i * 16);
        #pragma unroll
        for (int j = 0; j < 4; j++) {
            const int col = col0 + j * 8;
            const float bx = bias_s[col], by = bias_s[col + 1];
            float v0 = fmaxf(acc[i][j][0] + bx, 0.0f);
            float v1 = fmaxf(acc[i][j][1] + by, 0.0f);
            float v2 = fmaxf(acc[i][j][2] + bx, 0.0f);
            float v3 = fmaxf(acc[i][j][3] + by, 0.0f);
            *reinterpret_cast<__half2*>(Ce + r0 * Ntot + col)       = __floats2half2_rn(v0, v1);
            *reinterpret_cast<__half2*>(Ce + (r0 + 8) * Ntot + col) = __floats2half2_rn(v2, v3);
        }
    }
}

// ---------------- pre-pass: f32 -> f16 (vectorized) ----------------
__global__ void f32_to_f16_kernel(const float4* __restrict__ in, uint2* __restrict__ out,
                                  long n4) {
    long i = blockIdx.x * (long)blockDim.x + threadIdx.x;
    if (i < n4) {
        float4 v = in[i];
        __half2 lo = __floats2half2_rn(v.x, v.y);
        __half2 hi = __floats2half2_rn(v.z, v.w);
        uint2 o;
        o.x = *reinterpret_cast<uint32_t*>(&lo);
        o.y = *reinterpret_cast<uint32_t*>(&hi);
        out[i] = o;
    }
}

// ---------------- layer 3: out[b*E+e] = dot(h2[e,b,:], W3[e,:,0]) + b3[e] ----
__global__ void __launch_bounds__(256)
layer3_kernel(const __half* __restrict__ h2, const float* __restrict__ W3,
              const float* __restrict__ b3, float* __restrict__ out) {
    const int gw = (blockIdx.x * blockDim.x + threadIdx.x) >> 5;
    const int lane = threadIdx.x & 31;
    if (gw >= E_ * B_) return;
    const int e = gw / B_;
    const int b = gw % B_;
    const __half* h = h2 + ((size_t)e * B_ + b) * H2_;
    const float* w = W3 + (size_t)e * H2_;
    float s = 0.0f;
    #pragma unroll
    for (int i = 0; i < H2_ / 32; i++)
        s += __half2float(h[lane + 32 * i]) * w[lane + 32 * i];
    #pragma unroll
    for (int o = 16; o > 0; o >>= 1)
        s += __shfl_xor_sync(0xFFFFFFFFu, s, o);
    if (lane == 0) out[(size_t)b * E_ + e] = s + b3[e];
}

// ---------------- host ----------------
extern "C" void kernel_launch(void* const* d_in, const int* in_sizes, int n_in,
                              void* d_out, int out_size) {
    const float* x  = (const float*)d_in[0];
    const float* W1 = (const float*)d_in[1];
    const float* b1 = (const float*)d_in[2];
    const float* W2 = (const float*)d_in[3];
    const float* b2 = (const float*)d_in[4];
    const float* W3 = (const float*)d_in[5];
    const float* b3 = (const float*)d_in[6];
    float* out = (float*)d_out;

    __half *xh, *w1h, *w2h, *h1h, *h2h;
    cudaGetSymbolAddress((void**)&xh,  g_xh);
    cudaGetSymbolAddress((void**)&w1h, g_w1h);
    cudaGetSymbolAddress((void**)&w2h, g_w2h);
    cudaGetSymbolAddress((void**)&h1h, g_h1h);
    cudaGetSymbolAddress((void**)&h2h, g_h2h);

    cudaFuncSetAttribute(gemm_f16, cudaFuncAttributeMaxDynamicSharedMemorySize, SMEM_TOT);

    // pre-convert to fp16
    {
        long n4x  = (long)B_ * D_ / 4;
        long n4w1 = (long)E_ * D_ * H1_ / 4;
        long n4w2 = (long)E_ * H1_ * H2_ / 4;
        f32_to_f16_kernel<<<(unsigned)((n4x  + 255) / 256), 256>>>((const float4*)x,  (uint2*)xh,  n4x);
        f32_to_f16_kernel<<<(unsigned)((n4w1 + 255) / 256), 256>>>((const float4*)W1, (uint2*)w1h, n4w1);
        f32_to_f16_kernel<<<(unsigned)((n4w2 + 255) / 256), 256>>>((const float4*)W2, (uint2*)w2h, n4w2);
    }

    // layer 1: per-expert [1024,2048] x [2048,512], relu
    {
        dim3 grid(H1_ / NT, B_ / MT, E_);   // (4, 8, 100)
        gemm_f16<<<grid, 256, SMEM_TOT>>>(
            xh, w1h, b1, h1h,
            D_ / KC, /*ArowsPerE=*/0, /*Ntot=*/H1_,
            (unsigned long long)B_ * H1_);
    }
    // layer 2: per-expert [1024,512] x [512,256], relu
    {
        dim3 grid(H2_ / NT, B_ / MT, E_);   // (2, 8, 100)
        gemm_f16<<<grid, 256, SMEM_TOT>>>(
            h1h, w2h, b2, h2h,
            H1_ / KC, /*ArowsPerE=*/B_, /*Ntot=*/H2_,
            (unsigned long long)B_ * H2_);
    }
    // layer 3
    layer3_kernel<<<(E_ * B_) / 8, 256>>>(h2h, W3, b3, out);
}

// round 6
// speedup vs baseline: 2.1705x; 1.0111x over previous
#include <cuda_runtime.h>
#include <cuda_fp16.h>
#include <cstdint>

// ---------------- problem dims ----------------
#define E_  100
#define B_  1024
#define D_  2048
#define H1_ 512
#define H2_ 256

// ---------------- scratch (__device__ globals; no cudaMalloc allowed) ----
__device__ __half g_xh [(size_t)B_ * D_];          //   4MB
__device__ __half g_w1h[(size_t)E_ * D_ * H1_];    // 210MB
__device__ __half g_w2h[(size_t)E_ * H1_ * H2_];   //  26MB
__device__ __half g_h1h[(size_t)E_ * B_ * H1_];    // 105MB
__device__ __half g_h2h[(size_t)E_ * B_ * H2_];    //  52MB

// ---------------- device helpers ----------------
__device__ __forceinline__ uint32_t smem_u32(const void* p) {
    uint32_t a;
    asm("{ .reg .u64 t; cvta.to.shared.u64 t, %1; cvt.u32.u64 %0, t; }" : "=r"(a) : "l"(p));
    return a;
}
__device__ __forceinline__ void cp_async16(uint32_t s, const void* g) {
    asm volatile("cp.async.cg.shared.global [%0], [%1], 16;" :: "r"(s), "l"(g));
}
__device__ __forceinline__ void cp_commit() {
    asm volatile("cp.async.commit_group;" ::: "memory");
}
__device__ __forceinline__ void ldsm4(uint32_t r[4], uint32_t addr) {
    asm volatile("ldmatrix.sync.aligned.m8n8.x4.shared.b16 {%0,%1,%2,%3}, [%4];"
        : "=r"(r[0]), "=r"(r[1]), "=r"(r[2]), "=r"(r[3]) : "r"(addr));
}
__device__ __forceinline__ void ldsm4t(uint32_t& r0, uint32_t& r1, uint32_t& r2, uint32_t& r3,
                                       uint32_t addr) {
    asm volatile("ldmatrix.sync.aligned.m8n8.x4.trans.shared.b16 {%0,%1,%2,%3}, [%4];"
        : "=r"(r0), "=r"(r1), "=r"(r2), "=r"(r3) : "r"(addr));
}
__device__ __forceinline__ void mma_f16(float c[4], const uint32_t a[4], const uint32_t b[2]) {
    asm volatile(
        "mma.sync.aligned.m16n8k16.row.col.f32.f16.f16.f32 "
        "{%0,%1,%2,%3}, {%4,%5,%6,%7}, {%8,%9}, {%0,%1,%2,%3};"
        : "+f"(c[0]), "+f"(c[1]), "+f"(c[2]), "+f"(c[3])
        : "r"(a[0]), "r"(a[1]), "r"(a[2]), "r"(a[3]), "r"(b[0]), "r"(b[1]));
}

// ---------------- GEMM: C[e] = relu(A[e] @ B[e] + bias[e]) in fp16 -------
// CTA tile 128(M) x 128(N), K chunk 64. 256 threads = 8 warps (2m x 4n),
// warp tile 64x32. Register-level k-step pipelining: fragments for k-step
// ks+1 are prefetched (LDSM) while ks's 16 MMAs drain the tensor pipe.
#define MT 128
#define NT 128
#define KC 64
#define A_STRIDE 144                 // 64 fp16 = 128B data + 16B pad
#define B_STRIDE 272                 // 128 fp16 = 256B data + 16B pad
#define A_TILE_B (MT * A_STRIDE)     // 18432
#define B_TILE_B (KC * B_STRIDE)     // 17408
#define STAGE_B  (A_TILE_B + B_TILE_B)   // 35840
#define NSTAGE 3
#define SM_TILE_OFF 512
#define SMEM_TOT (SM_TILE_OFF + NSTAGE * STAGE_B)   // 108032

__global__ void __launch_bounds__(256)
gemm_f16(const __half* __restrict__ A, const __half* __restrict__ Bw,
         const float* __restrict__ bias, __half* __restrict__ C,
         int nch, int ArowsPerE, int Ntot, unsigned long long strideCe) {
    extern __shared__ __align__(128) char smem[];
    float* bias_s = reinterpret_cast<float*>(smem);
    const uint32_t sbase = smem_u32(smem) + SM_TILE_OFF;
    const int tid = threadIdx.x, lane = tid & 31, warp = tid >> 5;
    const int wm = warp >> 2, wn = warp & 3;
    const int e = blockIdx.z, mt = blockIdx.y, nt = blockIdx.x;
    const int n0 = nt * NT;
    const int K = nch * KC;

    if (tid < NT) bias_s[tid] = bias[(size_t)e * Ntot + n0 + tid];

    const char* Ab = (const char*)(A + ((size_t)e * ArowsPerE + (size_t)mt * MT) * K);
    const char* Bb = (const char*)(Bw + (size_t)e * (size_t)K * Ntot + n0);
    const int ldaB = K * 2;
    const int ldbB = Ntot * 2;

    auto load_stage = [&](int s, int c) {
        const uint32_t st = sbase + s * STAGE_B;
        const char* Ac = Ab + c * KC * 2;
        #pragma unroll
        for (int it = 0; it < 4; it++) {
            int q = tid + it * 256;              // 0..1023 (128 rows x 8 segs)
            int r = q >> 3, seg = (q & 7) * 16;
            cp_async16(st + r * A_STRIDE + seg, Ac + (size_t)r * ldaB + seg);
        }
        const char* Bc = Bb + (size_t)(c * KC) * ldbB;
        const uint32_t stb = st + A_TILE_B;
        #pragma unroll
        for (int it = 0; it < 4; it++) {
            int q = tid + it * 256;              // 0..1023 (64 rows x 16 segs)
            int r = q >> 4, seg = (q & 15) * 16;
            cp_async16(stb + r * B_STRIDE + seg, Bc + (size_t)r * ldbB + seg);
        }
    };

    // per-lane ldmatrix offsets (bytes)
    const uint32_t offA = (uint32_t)(lane & 15) * A_STRIDE + (uint32_t)(lane >> 4) * 16;
    const uint32_t offB = (uint32_t)(lane & 15) * B_STRIDE + (uint32_t)(lane >> 4) * 16;
    const uint32_t awoff = (uint32_t)wm * 64 * A_STRIDE + offA;
    const uint32_t bwoff = (uint32_t)wn * 64 + offB;          // wn*32 cols * 2B

    // double-buffered fragments
    uint32_t afr[2][4][4], bfr[2][4][2];

    auto prefetch = [&](uint32_t st, int ks, int buf) {
        const uint32_t sa = st + awoff + (uint32_t)ks * 32;
        #pragma unroll
        for (int i = 0; i < 4; i++)
            ldsm4(afr[buf][i], sa + (uint32_t)i * (16 * A_STRIDE));
        const uint32_t sb = st + A_TILE_B + bwoff + (uint32_t)ks * (16 * B_STRIDE);
        #pragma unroll
        for (int j2 = 0; j2 < 2; j2++) {
            uint32_t r0, r1, r2, r3;
            ldsm4t(r0, r1, r2, r3, sb + (uint32_t)j2 * 32);
            bfr[buf][j2 * 2][0] = r0;     bfr[buf][j2 * 2][1] = r1;
            bfr[buf][j2 * 2 + 1][0] = r2; bfr[buf][j2 * 2 + 1][1] = r3;
        }
    };

    float acc[4][4][4];
    #pragma unroll
    for (int i = 0; i < 4; i++)
        #pragma unroll
        for (int j = 0; j < 4; j++)
            #pragma unroll
            for (int r = 0; r < 4; r++) acc[i][j][r] = 0.0f;

    // ---- prologue ----
    load_stage(0, 0); cp_commit();
    load_stage(1, 1); cp_commit();
    asm volatile("cp.async.wait_group 1;" ::: "memory");
    __syncthreads();
    prefetch(sbase, 0, 0);

    // ---- mainloop ----
    for (int c = 0; c < nch; c++) {
        const uint32_t st = sbase + (c % NSTAGE) * STAGE_B;
        if (c + 2 < nch) { load_stage((c + 2) % NSTAGE, c + 2); cp_commit(); }

        #pragma unroll
        for (int ks = 0; ks < 4; ks++) {
            const int cur = ks & 1;
            if (ks < 3) prefetch(st, ks + 1, cur ^ 1);
            #pragma unroll
            for (int i = 0; i < 4; i++)
                #pragma unroll
                for (int j = 0; j < 4; j++)
                    mma_f16(acc[i][j], afr[cur][i], bfr[cur][j]);
        }

        if (c + 1 < nch) {
            if (c + 2 < nch) { asm volatile("cp.async.wait_group 1;" ::: "memory"); }
            else             { asm volatile("cp.async.wait_group 0;" ::: "memory"); }
            __syncthreads();
            prefetch(sbase + ((c + 1) % NSTAGE) * STAGE_B, 0, 0);
        }
    }

    // ---- epilogue: bias + relu, store fp16 ----
    const int mrow0 = mt * MT + wm * 64 + (lane >> 2);
    const int col0 = wn * 32 + (lane & 3) * 2;
    __half* Ce = C + (size_t)e * strideCe + n0;
    #pragma unroll
    for (int i = 0; i < 4; i++) {
        const size_t r0 = (size_t)(mrow0 + i * 16);
        #pragma unroll
        for (int j = 0; j < 4; j++) {
            const int col = col0 + j * 8;
            const float bx = bias_s[col], by = bias_s[col + 1];
            float v0 = fmaxf(acc[i][j][0] + bx, 0.0f);
            float v1 = fmaxf(acc[i][j][1] + by, 0.0f);
            float v2 = fmaxf(acc[i][j][2] + bx, 0.0f);
            float v3 = fmaxf(acc[i][j][3] + by, 0.0f);
            *reinterpret_cast<__half2*>(Ce + r0 * Ntot + col)       = __floats2half2_rn(v0, v1);
            *reinterpret_cast<__half2*>(Ce + (r0 + 8) * Ntot + col) = __floats2half2_rn(v2, v3);
        }
    }
}

// ---------------- pre-pass: f32 -> f16 (vectorized) ----------------
__global__ void f32_to_f16_kernel(const float4* __restrict__ in, uint2* __restrict__ out,
                                  long n4) {
    long i = blockIdx.x * (long)blockDim.x + threadIdx.x;
    if (i < n4) {
        float4 v = in[i];
        __half2 lo = __floats2half2_rn(v.x, v.y);
        __half2 hi = __floats2half2_rn(v.z, v.w);
        uint2 o;
        o.x = *reinterpret_cast<uint32_t*>(&lo);
        o.y = *reinterpret_cast<uint32_t*>(&hi);
        out[i] = o;
    }
}

// ---------------- layer 3: out[b*E+e] = dot(h2[e,b,:], W3[e,:,0]) + b3[e] ----
__global__ void __launch_bounds__(256)
layer3_kernel(const __half* __restrict__ h2, const float* __restrict__ W3,
              const float* __restrict__ b3, float* __restrict__ out) {
    const int gw = (blockIdx.x * blockDim.x + threadIdx.x) >> 5;
    const int lane = threadIdx.x & 31;
    if (gw >= E_ * B_) return;
    const int e = gw / B_;
    const int b = gw % B_;
    const __half* h = h2 + ((size_t)e * B_ + b) * H2_;
    const float* w = W3 + (size_t)e * H2_;
    float s = 0.0f;
    #pragma unroll
    for (int i = 0; i < H2_ / 32; i++)
        s += __half2float(h[lane + 32 * i]) * w[lane + 32 * i];
    #pragma unroll
    for (int o = 16; o > 0; o >>= 1)
        s += __shfl_xor_sync(0xFFFFFFFFu, s, o);
    if (lane == 0) out[(size_t)b * E_ + e] = s + b3[e];
}

// ---------------- host ----------------
extern "C" void kernel_launch(void* const* d_in, const int* in_sizes, int n_in,
                              void* d_out, int out_size) {
    const float* x  = (const float*)d_in[0];
    const float* W1 = (const float*)d_in[1];
    const float* b1 = (const float*)d_in[2];
    const float* W2 = (const float*)d_in[3];
    const float* b2 = (const float*)d_in[4];
    const float* W3 = (const float*)d_in[5];
    const float* b3 = (const float*)d_in[6];
    float* out = (float*)d_out;

    __half *xh, *w1h, *w2h, *h1h, *h2h;
    cudaGetSymbolAddress((void**)&xh,  g_xh);
    cudaGetSymbolAddress((void**)&w1h, g_w1h);
    cudaGetSymbolAddress((void**)&w2h, g_w2h);
    cudaGetSymbolAddress((void**)&h1h, g_h1h);
    cudaGetSymbolAddress((void**)&h2h, g_h2h);

    cudaFuncSetAttribute(gemm_f16, cudaFuncAttributeMaxDynamicSharedMemorySize, SMEM_TOT);

    // pre-convert to fp16
    {
        long n4x  = (long)B_ * D_ / 4;
        long n4w1 = (long)E_ * D_ * H1_ / 4;
        long n4w2 = (long)E_ * H1_ * H2_ / 4;
        f32_to_f16_kernel<<<(unsigned)((n4x  + 255) / 256), 256>>>((const float4*)x,  (uint2*)xh,  n4x);
        f32_to_f16_kernel<<<(unsigned)((n4w1 + 255) / 256), 256>>>((const float4*)W1, (uint2*)w1h, n4w1);
        f32_to_f16_kernel<<<(unsigned)((n4w2 + 255) / 256), 256>>>((const float4*)W2, (uint2*)w2h, n4w2);
    }

    // layer 1: per-expert [1024,2048] x [2048,512], relu
    {
        dim3 grid(H1_ / NT, B_ / MT, E_);   // (4, 8, 100)
        gemm_f16<<<grid, 256, SMEM_TOT>>>(
            xh, w1h, b1, h1h,
            D_ / KC, /*ArowsPerE=*/0, /*Ntot=*/H1_,
            (unsigned long long)B_ * H1_);
    }
    // layer 2: per-expert [1024,512] x [512,256], relu
    {
        dim3 grid(H2_ / NT, B_ / MT, E_);   // (2, 8, 100)
        gemm_f16<<<grid, 256, SMEM_TOT>>>(
            h1h, w2h, b2, h2h,
            H1_ / KC, /*ArowsPerE=*/B_, /*Ntot=*/H2_,
            (unsigned long long)B_ * H2_);
    }
    // layer 3
    layer3_kernel<<<(E_ * B_) / 8, 256>>>(h2h, W3, b3, out);
}

// round 7
// speedup vs baseline: 2.3212x; 1.0694x over previous
#include <cuda_runtime.h>
#include <cuda_fp16.h>
#include <cstdint>

// ---------------- problem dims ----------------
#define E_  100
#define B_  1024
#define D_  2048
#define H1_ 512
#define H2_ 256

// ---------------- scratch (__device__ globals; no cudaMalloc allowed) ----
__device__ __half g_xh [(size_t)B_ * D_];          //   4MB
__device__ __half g_w1h[(size_t)E_ * D_ * H1_];    // 210MB
__device__ __half g_w2h[(size_t)E_ * H1_ * H2_];   //  26MB
__device__ __half g_h1h[(size_t)E_ * B_ * H1_];    // 105MB
__device__ __half g_h2h[(size_t)E_ * B_ * H2_];    //  52MB

// ---------------- device helpers ----------------
__device__ __forceinline__ uint32_t smem_u32(const void* p) {
    uint32_t a;
    asm("{ .reg .u64 t; cvta.to.shared.u64 t, %1; cvt.u32.u64 %0, t; }" : "=r"(a) : "l"(p));
    return a;
}
__device__ __forceinline__ void cp_async16(uint32_t s, const void* g) {
    asm volatile("cp.async.cg.shared.global [%0], [%1], 16;" :: "r"(s), "l"(g));
}
__device__ __forceinline__ void cp_commit() {
    asm volatile("cp.async.commit_group;" ::: "memory");
}
__device__ __forceinline__ void ldsm4(uint32_t r[4], uint32_t addr) {
    asm volatile("ldmatrix.sync.aligned.m8n8.x4.shared.b16 {%0,%1,%2,%3}, [%4];"
        : "=r"(r[0]), "=r"(r[1]), "=r"(r[2]), "=r"(r[3]) : "r"(addr));
}
__device__ __forceinline__ void ldsm4t(uint32_t& r0, uint32_t& r1, uint32_t& r2, uint32_t& r3,
                                       uint32_t addr) {
    asm volatile("ldmatrix.sync.aligned.m8n8.x4.trans.shared.b16 {%0,%1,%2,%3}, [%4];"
        : "=r"(r0), "=r"(r1), "=r"(r2), "=r"(r3) : "r"(addr));
}
__device__ __forceinline__ void mma_f16(float c[4], const uint32_t a[4], const uint32_t b[2]) {
    asm volatile(
        "mma.sync.aligned.m16n8k16.row.col.f32.f16.f16.f32 "
        "{%0,%1,%2,%3}, {%4,%5,%6,%7}, {%8,%9}, {%0,%1,%2,%3};"
        : "+f"(c[0]), "+f"(c[1]), "+f"(c[2]), "+f"(c[3])
        : "r"(a[0]), "r"(a[1]), "r"(a[2]), "r"(a[3]), "r"(b[0]), "r"(b[1]));
}

// ---------------- GEMM: C[e] = relu(A[e] @ B[e] + bias[e]) in fp16 -------
// CTA tile 128(M) x 128(N), K chunk 64. 128 threads = 4 warps (2m x 2n),
// warp tile 64x64 -> halved LDSM redundancy vs 64x32; smem crossbar no
// longer co-saturates with the tensor pipe. 2 CTAs/SM.
#define MT 128
#define NT 128
#define KC 64
#define A_STRIDE 144                 // 64 fp16 = 128B data + 16B pad
#define B_STRIDE 272                 // 128 fp16 = 256B data + 16B pad
#define A_TILE_B (MT * A_STRIDE)     // 18432
#define B_TILE_B (KC * B_STRIDE)     // 17408
#define STAGE_B  (A_TILE_B + B_TILE_B)   // 35840
#define NSTAGE 3
#define SM_TILE_OFF 512
#define SMEM_TOT (SM_TILE_OFF + NSTAGE * STAGE_B)   // 108032

__global__ void __launch_bounds__(128, 2)
gemm_f16(const __half* __restrict__ A, const __half* __restrict__ Bw,
         const float* __restrict__ bias, __half* __restrict__ C,
         int nch, int ArowsPerE, int Ntot, unsigned long long strideCe) {
    extern __shared__ __align__(128) char smem[];
    float* bias_s = reinterpret_cast<float*>(smem);
    const uint32_t sbase = smem_u32(smem) + SM_TILE_OFF;
    const int tid = threadIdx.x, lane = tid & 31, warp = tid >> 5;
    const int wm = warp >> 1, wn = warp & 1;
    const int e = blockIdx.z, mt = blockIdx.y, nt = blockIdx.x;
    const int n0 = nt * NT;
    const int K = nch * KC;

    if (tid < NT) bias_s[tid] = bias[(size_t)e * Ntot + n0 + tid];

    const char* Ab = (const char*)(A + ((size_t)e * ArowsPerE + (size_t)mt * MT) * K);
    const char* Bb = (const char*)(Bw + (size_t)e * (size_t)K * Ntot + n0);
    const int ldaB = K * 2;
    const int ldbB = Ntot * 2;

    auto load_stage = [&](int s, int c) {
        const uint32_t st = sbase + s * STAGE_B;
        const char* Ac = Ab + c * KC * 2;
        #pragma unroll
        for (int it = 0; it < 8; it++) {
            int q = tid + it * 128;              // 0..1023 (128 rows x 8 segs)
            int r = q >> 3, seg = (q & 7) * 16;
            cp_async16(st + r * A_STRIDE + seg, Ac + (size_t)r * ldaB + seg);
        }
        const char* Bc = Bb + (size_t)(c * KC) * ldbB;
        const uint32_t stb = st + A_TILE_B;
        #pragma unroll
        for (int it = 0; it < 8; it++) {
            int q = tid + it * 128;              // 0..1023 (64 rows x 16 segs)
            int r = q >> 4, seg = (q & 15) * 16;
            cp_async16(stb + r * B_STRIDE + seg, Bc + (size_t)r * ldbB + seg);
        }
    };

    // per-lane ldmatrix offsets (bytes)
    const uint32_t offA = (uint32_t)(lane & 15) * A_STRIDE + (uint32_t)(lane >> 4) * 16;
    const uint32_t offB = (uint32_t)(lane & 15) * B_STRIDE + (uint32_t)(lane >> 4) * 16;
    const uint32_t awoff = (uint32_t)wm * 64 * A_STRIDE + offA;
    const uint32_t bwoff = (uint32_t)wn * 128 + offB;         // wn*64 cols * 2B

    // double-buffered fragments: A 4 m16-tiles, B 8 n8-blocks
    uint32_t afr[2][4][4], bfr[2][8][2];

    auto prefetch = [&](uint32_t st, int ks, int buf) {
        const uint32_t sa = st + awoff + (uint32_t)ks * 32;
        #pragma unroll
        for (int i = 0; i < 4; i++)
            ldsm4(afr[buf][i], sa + (uint32_t)i * (16 * A_STRIDE));
        const uint32_t sb = st + A_TILE_B + bwoff + (uint32_t)ks * (16 * B_STRIDE);
        #pragma unroll
        for (int j2 = 0; j2 < 4; j2++) {
            uint32_t r0, r1, r2, r3;
            ldsm4t(r0, r1, r2, r3, sb + (uint32_t)j2 * 32);
            bfr[buf][j2 * 2][0] = r0;     bfr[buf][j2 * 2][1] = r1;
            bfr[buf][j2 * 2 + 1][0] = r2; bfr[buf][j2 * 2 + 1][1] = r3;
        }
    };

    float acc[4][8][4];
    #pragma unroll
    for (int i = 0; i < 4; i++)
        #pragma unroll
        for (int j = 0; j < 8; j++)
            #pragma unroll
            for (int r = 0; r < 4; r++) acc[i][j][r] = 0.0f;

    // ---- prologue ----
    load_stage(0, 0); cp_commit();
    load_stage(1, 1); cp_commit();
    asm volatile("cp.async.wait_group 1;" ::: "memory");
    __syncthreads();
    prefetch(sbase, 0, 0);

    // ---- mainloop ----
    for (int c = 0; c < nch; c++) {
        const uint32_t st = sbase + (c % NSTAGE) * STAGE_B;
        if (c + 2 < nch) { load_stage((c + 2) % NSTAGE, c + 2); cp_commit(); }

        #pragma unroll
        for (int ks = 0; ks < 4; ks++) {
            const int cur = ks & 1;
            if (ks < 3) prefetch(st, ks + 1, cur ^ 1);
            #pragma unroll
            for (int i = 0; i < 4; i++)
                #pragma unroll
                for (int j = 0; j < 8; j++)
                    mma_f16(acc[i][j], afr[cur][i], bfr[cur][j]);
        }

        if (c + 1 < nch) {
            if (c + 2 < nch) { asm volatile("cp.async.wait_group 1;" ::: "memory"); }
            else             { asm volatile("cp.async.wait_group 0;" ::: "memory"); }
            __syncthreads();
            prefetch(sbase + ((c + 1) % NSTAGE) * STAGE_B, 0, 0);
        }
    }

    // ---- epilogue: bias + relu, store fp16 ----
    const int mrow0 = mt * MT + wm * 64 + (lane >> 2);
    const int col0 = wn * 64 + (lane & 3) * 2;
    __half* Ce = C + (size_t)e * strideCe + n0;
    #pragma unroll
    for (int i = 0; i < 4; i++) {
        const size_t r0 = (size_t)(mrow0 + i * 16);
        #pragma unroll
        for (int j = 0; j < 8; j++) {
            const int col = col0 + j * 8;
            const float bx = bias_s[col], by = bias_s[col + 1];
            float v0 = fmaxf(acc[i][j][0] + bx, 0.0f);
            float v1 = fmaxf(acc[i][j][1] + by, 0.0f);
            float v2 = fmaxf(acc[i][j][2] + bx, 0.0f);
            float v3 = fmaxf(acc[i][j][3] + by, 0.0f);
            *reinterpret_cast<__half2*>(Ce + r0 * Ntot + col)       = __floats2half2_rn(v0, v1);
            *reinterpret_cast<__half2*>(Ce + (r0 + 8) * Ntot + col) = __floats2half2_rn(v2, v3);
        }
    }
}

// ---------------- pre-pass: f32 -> f16 (vectorized) ----------------
__global__ void f32_to_f16_kernel(const float4* __restrict__ in, uint2* __restrict__ out,
                                  long n4) {
    long i = blockIdx.x * (long)blockDim.x + threadIdx.x;
    if (i < n4) {
        float4 v = in[i];
        __half2 lo = __floats2half2_rn(v.x, v.y);
        __half2 hi = __floats2half2_rn(v.z, v.w);
        uint2 o;
        o.x = *reinterpret_cast<uint32_t*>(&lo);
        o.y = *reinterpret_cast<uint32_t*>(&hi);
        out[i] = o;
    }
}

// ---------------- layer 3: out[b*E+e] = dot(h2[e,b,:], W3[e,:,0]) + b3[e] ----
__global__ void __launch_bounds__(256)
layer3_kernel(const __half* __restrict__ h2, const float* __restrict__ W3,
              const float* __restrict__ b3, float* __restrict__ out) {
    const int gw = (blockIdx.x * blockDim.x + threadIdx.x) >> 5;
    const int lane = threadIdx.x & 31;
    if (gw >= E_ * B_) return;
    const int e = gw / B_;
    const int b = gw % B_;
    const __half* h = h2 + ((size_t)e * B_ + b) * H2_;
    const float* w = W3 + (size_t)e * H2_;
    float s = 0.0f;
    #pragma unroll
    for (int i = 0; i < H2_ / 32; i++)
        s += __half2float(h[lane + 32 * i]) * w[lane + 32 * i];
    #pragma unroll
    for (int o = 16; o > 0; o >>= 1)
        s += __shfl_xor_sync(0xFFFFFFFFu, s, o);
    if (lane == 0) out[(size_t)b * E_ + e] = s + b3[e];
}

// ---------------- host ----------------
extern "C" void kernel_launch(void* const* d_in, const int* in_sizes, int n_in,
                              void* d_out, int out_size) {
    const float* x  = (const float*)d_in[0];
    const float* W1 = (const float*)d_in[1];
    const float* b1 = (const float*)d_in[2];
    const float* W2 = (const float*)d_in[3];
    const float* b2 = (const float*)d_in[4];
    const float* W3 = (const float*)d_in[5];
    const float* b3 = (const float*)d_in[6];
    float* out = (float*)d_out;

    __half *xh, *w1h, *w2h, *h1h, *h2h;
    cudaGetSymbolAddress((void**)&xh,  g_xh);
    cudaGetSymbolAddress((void**)&w1h, g_w1h);
    cudaGetSymbolAddress((void**)&w2h, g_w2h);
    cudaGetSymbolAddress((void**)&h1h, g_h1h);
    cudaGetSymbolAddress((void**)&h2h, g_h2h);

    cudaFuncSetAttribute(gemm_f16, cudaFuncAttributeMaxDynamicSharedMemorySize, SMEM_TOT);

    // pre-convert to fp16
    {
        long n4x  = (long)B_ * D_ / 4;
        long n4w1 = (long)E_ * D_ * H1_ / 4;
        long n4w2 = (long)E_ * H1_ * H2_ / 4;
        f32_to_f16_kernel<<<(unsigned)((n4x  + 255) / 256), 256>>>((const float4*)x,  (uint2*)xh,  n4x);
        f32_to_f16_kernel<<<(unsigned)((n4w1 + 255) / 256), 256>>>((const float4*)W1, (uint2*)w1h, n4w1);
        f32_to_f16_kernel<<<(unsigned)((n4w2 + 255) / 256), 256>>>((const float4*)W2, (uint2*)w2h, n4w2);
    }

    // layer 1: per-expert [1024,2048] x [2048,512], relu
    {
        dim3 grid(H1_ / NT, B_ / MT, E_);   // (4, 8, 100)
        gemm_f16<<<grid, 128, SMEM_TOT>>>(
            xh, w1h, b1, h1h,
            D_ / KC, /*ArowsPerE=*/0, /*Ntot=*/H1_,
            (unsigned long long)B_ * H1_);
    }
    // layer 2: per-expert [1024,512] x [512,256], relu
    {
        dim3 grid(H2_ / NT, B_ / MT, E_);   // (2, 8, 100)
        gemm_f16<<<grid, 128, SMEM_TOT>>>(
            h1h, w2h, b2, h2h,
            H1_ / KC, /*ArowsPerE=*/B_, /*Ntot=*/H2_,
            (unsigned long long)B_ * H2_);
    }
    // layer 3
    layer3_kernel<<<(E_ * B_) / 8, 256>>>(h2h, W3, b3, out);
}